// round 2
// baseline (speedup 1.0000x reference)
#include <cuda_runtime.h>
#include <math.h>

#define BB 32
#define CC 4
#define LL 5
#define HH 360
#define WW 640
#define PP (HH * WW)   // 230400

#define DELTA_V 1.0f
#define DELTA_D 6.0f

#define BLOCKS_PER_BATCH 64
#define TPB 256

// ---- scratch (allocation-free rule: __device__ globals) ----
__device__ float g_sums[BB][LL][CC];
__device__ float g_counts[BB][LL];
__device__ float g_means[BB][LL + 1][CC];  // extended: index 0 = zeros
__device__ int   g_valid[BB][LL + 1];      // extended: index 0 = false
__device__ float g_point_count;
__device__ float g_dist_sum;

// ---- kernel 0: zero the accumulators ----
__global__ void k_init() {
    int i = threadIdx.x;
    float* s = &g_sums[0][0][0];
    for (int j = i; j < BB * LL * CC; j += blockDim.x) s[j] = 0.f;
    float* c = &g_counts[0][0];
    for (int j = i; j < BB * LL; j += blockDim.x) c[j] = 0.f;
    if (i == 0) { g_dist_sum = 0.f; g_point_count = 0.f; }
}

// ---- kernel 1: per-(batch,lane) sums + counts ----
__global__ __launch_bounds__(TPB) void k_accum(const int* __restrict__ tgt,
                                               const float* __restrict__ emb) {
    int b   = blockIdx.x / BLOCKS_PER_BATCH;
    int sub = blockIdx.x % BLOCKS_PER_BATCH;
    const int*   t = tgt + (size_t)b * PP;
    const float* e = emb + (size_t)b * CC * PP;

    float acc[LL][CC];
    float cnt[LL];
#pragma unroll
    for (int l = 0; l < LL; l++) {
        cnt[l] = 0.f;
#pragma unroll
        for (int c = 0; c < CC; c++) acc[l][c] = 0.f;
    }

    for (int p = sub * TPB + threadIdx.x; p < PP; p += BLOCKS_PER_BATCH * TPB) {
        int lab = t[p];
        float e0 = e[p];
        float e1 = e[PP + p];
        float e2 = e[2 * PP + p];
        float e3 = e[3 * PP + p];
#pragma unroll
        for (int l = 0; l < LL; l++) {
            if (lab == l + 1) {
                cnt[l] += 1.f;
                acc[l][0] += e0; acc[l][1] += e1;
                acc[l][2] += e2; acc[l][3] += e3;
            }
        }
    }

    __shared__ float s_acc[LL][CC];
    __shared__ float s_cnt[LL];
    if (threadIdx.x < LL * CC) (&s_acc[0][0])[threadIdx.x] = 0.f;
    if (threadIdx.x < LL) s_cnt[threadIdx.x] = 0.f;
    __syncthreads();

    const unsigned fm = 0xffffffffu;
#pragma unroll
    for (int l = 0; l < LL; l++) {
#pragma unroll
        for (int c = 0; c < CC; c++) {
            float v = acc[l][c];
#pragma unroll
            for (int o = 16; o > 0; o >>= 1) v += __shfl_xor_sync(fm, v, o);
            if ((threadIdx.x & 31) == 0) atomicAdd(&s_acc[l][c], v);
        }
        float v = cnt[l];
#pragma unroll
        for (int o = 16; o > 0; o >>= 1) v += __shfl_xor_sync(fm, v, o);
        if ((threadIdx.x & 31) == 0) atomicAdd(&s_cnt[l], v);
    }
    __syncthreads();

    if (threadIdx.x < LL * CC)
        atomicAdd(&g_sums[b][0][0] + threadIdx.x, (&s_acc[0][0])[threadIdx.x]);
    if (threadIdx.x < LL)
        atomicAdd(&g_counts[b][threadIdx.x], s_cnt[threadIdx.x]);
}

// ---- kernel 2: means, valid flags, point_count (single block) ----
__global__ void k_means() {
    int i = threadIdx.x;  // 256 threads
    __shared__ float s_pc[256];
    float pc = 0.f;
    if (i < BB * LL) {
        int b = i / LL, l = i % LL;
        float cf = g_counts[b][l];
        int v = (cf > 1.f) ? 1 : 0;
        g_valid[b][l + 1] = v;
        float inv = 1.f / fmaxf(cf, 1.f);
#pragma unroll
        for (int c = 0; c < CC; c++) g_means[b][l + 1][c] = g_sums[b][l][c] * inv;
        if (v) pc = cf;
    }
    if (i < BB) {
        g_valid[i][0] = 0;
#pragma unroll
        for (int c = 0; c < CC; c++) g_means[i][0][c] = 0.f;
    }
    s_pc[i] = pc;
    __syncthreads();
    for (int s = 128; s > 0; s >>= 1) {
        if (i < s) s_pc[i] += s_pc[i + s];
        __syncthreads();
    }
    if (i == 0) g_point_count = s_pc[0];
}

// ---- kernel 3: per-pixel hinge pull loss ----
__global__ __launch_bounds__(TPB) void k_dist(const int* __restrict__ tgt,
                                              const float* __restrict__ emb) {
    int b   = blockIdx.x / BLOCKS_PER_BATCH;
    int sub = blockIdx.x % BLOCKS_PER_BATCH;

    __shared__ float s_m[LL + 1][CC];
    __shared__ int   s_v[LL + 1];
    if (threadIdx.x < (LL + 1) * CC)
        (&s_m[0][0])[threadIdx.x] = (&g_means[b][0][0])[threadIdx.x];
    if (threadIdx.x < LL + 1) s_v[threadIdx.x] = g_valid[b][threadIdx.x];
    __syncthreads();

    const int*   t = tgt + (size_t)b * PP;
    const float* e = emb + (size_t)b * CC * PP;

    float acc = 0.f;
    for (int p = sub * TPB + threadIdx.x; p < PP; p += BLOCKS_PER_BATCH * TPB) {
        int lab = t[p];
        if (s_v[lab]) {
            float d0 = e[p]          - s_m[lab][0];
            float d1 = e[PP + p]     - s_m[lab][1];
            float d2 = e[2 * PP + p] - s_m[lab][2];
            float d3 = e[3 * PP + p] - s_m[lab][3];
            float sq = d0 * d0 + d1 * d1 + d2 * d2 + d3 * d3;
            float dist = sqrtf(fmaxf(sq, 1e-12f));
            float h = fmaxf(dist - DELTA_V, 0.f);
            acc += h * h;
        }
    }

    const unsigned fm = 0xffffffffu;
#pragma unroll
    for (int o = 16; o > 0; o >>= 1) acc += __shfl_xor_sync(fm, acc, o);
    __shared__ float s_w[TPB / 32];
    if ((threadIdx.x & 31) == 0) s_w[threadIdx.x >> 5] = acc;
    __syncthreads();
    if (threadIdx.x == 0) {
        float s = 0.f;
#pragma unroll
        for (int w = 0; w < TPB / 32; w++) s += s_w[w];
        atomicAdd(&g_dist_sum, s);
    }
}

// ---- kernel 4: pairwise push loss + final combine (1 warp) ----
__global__ void k_final(float* __restrict__ out) {
    int b = threadIdx.x;  // 32 threads, one per batch
    float m[LL][CC];
    int v[LL];
#pragma unroll
    for (int l = 0; l < LL; l++) {
        v[l] = g_valid[b][l + 1];
#pragma unroll
        for (int c = 0; c < CC; c++) m[l][c] = g_means[b][l + 1][c];
    }
    float psum = 0.f, np = 0.f;
#pragma unroll
    for (int i = 0; i < LL; i++) {
#pragma unroll
        for (int j = i + 1; j < LL; j++) {
            if (v[i] && v[j]) {
                float sq = 0.f;
#pragma unroll
                for (int c = 0; c < CC; c++) {
                    float d = m[i][c] - m[j][c];
                    sq += d * d;
                }
                float pd = sqrtf(fmaxf(sq, 1e-12f));
                float ph = fmaxf(DELTA_D - pd, 0.f);
                psum += ph * ph;
                np += 1.f;
            }
        }
    }
    float var_b = (np > 0.f) ? (psum / np) : 0.f;
    float has   = (np > 0.f) ? 1.f : 0.f;
    const unsigned fm = 0xffffffffu;
#pragma unroll
    for (int o = 16; o > 0; o >>= 1) {
        var_b += __shfl_xor_sync(fm, var_b, o);
        has   += __shfl_xor_sync(fm, has, o);
    }
    if (b == 0) {
        float var_loss = (has > 0.f) ? (var_b / has) : 0.f;
        float pc = g_point_count;
        float dl = (pc > 0.f) ? (g_dist_sum / fmaxf(pc, 1.f)) : 0.f;
        out[0] = dl + var_loss;
    }
}

extern "C" void kernel_launch(void* const* d_in, const int* in_sizes, int n_in,
                              void* d_out, int out_size) {
    const int*   targets = (const int*)d_in[0];
    const float* emb     = (const float*)d_in[1];
    float*       out     = (float*)d_out;

    k_init<<<1, 256>>>();
    k_accum<<<BB * BLOCKS_PER_BATCH, TPB>>>(targets, emb);
    k_means<<<1, 256>>>();
    k_dist<<<BB * BLOCKS_PER_BATCH, TPB>>>(targets, emb);
    k_final<<<1, 32>>>(out);
}

// round 4
// speedup vs baseline: 1.3167x; 1.3167x over previous
#include <cuda_runtime.h>
#include <math.h>

#define BB 32
#define CC 4
#define LL 5
#define PP 230400          // 360*640
#define PP4 (PP / 4)       // 57600 float4 per channel per batch

#define DELTA_V 1.0f
#define DELTA_D 6.0f

#define BPB 45             // blocks per batch
#define TPB 256
#define ITERS (PP4 / (BPB * TPB))   // 5, exact
#define NVALS 30           // 20 sums (l*4+c) + 5 counts + padding-free
#define NBLK (BB * BPB)    // 1440

// ---- scratch (allocation-free rule: __device__ globals) ----
__device__ float g_part[BB][BPB][NVALS];   // per-block partial sums+counts
__device__ float g_means4[BB][LL + 1][CC]; // extended means, lane 0 = zeros
__device__ float g_validf[BB][LL + 1];     // 0/1 floats, lane 0 = 0
__device__ float g_pc[BB];                 // per-batch point count
__device__ float g_pdist[NBLK];            // per-block dist partials

// ================= kernel 1: per-(batch,lane) sums + counts =================
__global__ __launch_bounds__(TPB) void k_accum(const int* __restrict__ tgt,
                                               const float* __restrict__ emb) {
    const int b   = blockIdx.x / BPB;
    const int sub = blockIdx.x % BPB;
    const int4*   t4 = (const int4*)(tgt + (size_t)b * PP);
    const float4* e0 = (const float4*)(emb + (size_t)b * CC * PP);
    const float4* e1 = e0 + PP4;
    const float4* e2 = e1 + PP4;
    const float4* e3 = e2 + PP4;

    float acc[LL][CC];
    float cnt[LL];
#pragma unroll
    for (int l = 0; l < LL; l++) {
        cnt[l] = 0.f;
#pragma unroll
        for (int c = 0; c < CC; c++) acc[l][c] = 0.f;
    }

#pragma unroll
    for (int i = 0; i < ITERS; i++) {
        int p = (i * BPB + sub) * TPB + threadIdx.x;
        int4   tv = t4[p];
        float4 v0 = e0[p];
        float4 v1 = e1[p];
        float4 v2 = e2[p];
        float4 v3 = e3[p];
        int   labs[4] = {tv.x, tv.y, tv.z, tv.w};
        float ex[4]   = {v0.x, v0.y, v0.z, v0.w};
        float ey[4]   = {v1.x, v1.y, v1.z, v1.w};
        float ez[4]   = {v2.x, v2.y, v2.z, v2.w};
        float ew[4]   = {v3.x, v3.y, v3.z, v3.w};
#pragma unroll
        for (int j = 0; j < 4; j++) {
            int lab = labs[j];
#pragma unroll
            for (int l = 0; l < LL; l++) {
                if (lab == l + 1) {
                    cnt[l] += 1.f;
                    acc[l][0] += ex[j]; acc[l][1] += ey[j];
                    acc[l][2] += ez[j]; acc[l][3] += ew[j];
                }
            }
        }
    }

    // deterministic block reduction: warp shuffle -> shared -> thread scan
    __shared__ float s_part[TPB / 32][NVALS];
    const unsigned fm = 0xffffffffu;
    int wid = threadIdx.x >> 5, lid = threadIdx.x & 31;
#pragma unroll
    for (int l = 0; l < LL; l++) {
#pragma unroll
        for (int c = 0; c < CC; c++) {
            float v = acc[l][c];
#pragma unroll
            for (int o = 16; o > 0; o >>= 1) v += __shfl_xor_sync(fm, v, o);
            if (lid == 0) s_part[wid][l * CC + c] = v;
        }
        float v = cnt[l];
#pragma unroll
        for (int o = 16; o > 0; o >>= 1) v += __shfl_xor_sync(fm, v, o);
        if (lid == 0) s_part[wid][20 + l] = v;
    }
    __syncthreads();
    if (threadIdx.x < NVALS - 5) {  // 25 real values
        float s = 0.f;
#pragma unroll
        for (int w = 0; w < TPB / 32; w++) s += s_part[w][threadIdx.x];
        g_part[b][sub][threadIdx.x] = s;
    }
}

// ================= kernel 2: means, valid, point_count (32 blocks) ==========
__global__ void k_means() {
    int b = blockIdx.x;
    __shared__ float s_red[25][8];
    __shared__ float s_val[25];
    int tid = threadIdx.x;  // 256
    if (tid < 200) {
        int j = tid / 8, k = tid % 8;
        float s = 0.f;
        for (int sub = k; sub < BPB; sub += 8) s += g_part[b][sub][j];
        s_red[j][k] = s;
    }
    __syncthreads();
    if (tid < 25) {
        float s = 0.f;
#pragma unroll
        for (int k = 0; k < 8; k++) s += s_red[tid][k];
        s_val[tid] = s;
    }
    __syncthreads();
    if (tid < LL) {
        float cf = s_val[20 + tid];
        float v  = (cf > 1.f) ? 1.f : 0.f;
        g_validf[b][tid + 1] = v;
        float inv = 1.f / fmaxf(cf, 1.f);
#pragma unroll
        for (int c = 0; c < CC; c++)
            g_means4[b][tid + 1][c] = s_val[tid * CC + c] * inv;
    }
    if (tid == 0) {
        g_validf[b][0] = 0.f;
#pragma unroll
        for (int c = 0; c < CC; c++) g_means4[b][0][c] = 0.f;
        float pc = 0.f;
#pragma unroll
        for (int l = 0; l < LL; l++) {
            float cf = s_val[20 + l];
            if (cf > 1.f) pc += cf;
        }
        g_pc[b] = pc;
    }
}

// ================= kernel 3: per-pixel hinge pull loss ======================
__global__ __launch_bounds__(TPB) void k_dist(const int* __restrict__ tgt,
                                              const float* __restrict__ emb) {
    const int b   = blockIdx.x / BPB;
    const int sub = blockIdx.x % BPB;

    __shared__ float4 s_m[LL + 1];
    __shared__ float  s_vf[LL + 1];
    if (threadIdx.x < LL + 1) {
        s_m[threadIdx.x] = make_float4(g_means4[b][threadIdx.x][0],
                                       g_means4[b][threadIdx.x][1],
                                       g_means4[b][threadIdx.x][2],
                                       g_means4[b][threadIdx.x][3]);
        s_vf[threadIdx.x] = g_validf[b][threadIdx.x];
    }
    __syncthreads();

    const int4*   t4 = (const int4*)(tgt + (size_t)b * PP);
    const float4* e0 = (const float4*)(emb + (size_t)b * CC * PP);
    const float4* e1 = e0 + PP4;
    const float4* e2 = e1 + PP4;
    const float4* e3 = e2 + PP4;

    float acc = 0.f;
    // reverse order: start where k_accum finished -> maximize L2 hits
#pragma unroll
    for (int i = ITERS - 1; i >= 0; i--) {
        int p = (i * BPB + sub) * TPB + threadIdx.x;
        int4   tv = t4[p];
        float4 v0 = e0[p];
        float4 v1 = e1[p];
        float4 v2 = e2[p];
        float4 v3 = e3[p];
        int   labs[4] = {tv.x, tv.y, tv.z, tv.w};
        float ex[4]   = {v0.x, v0.y, v0.z, v0.w};
        float ey[4]   = {v1.x, v1.y, v1.z, v1.w};
        float ez[4]   = {v2.x, v2.y, v2.z, v2.w};
        float ew[4]   = {v3.x, v3.y, v3.z, v3.w};
#pragma unroll
        for (int j = 0; j < 4; j++) {
            int lab = labs[j];
            float4 m = s_m[lab];
            float d0 = ex[j] - m.x;
            float d1 = ey[j] - m.y;
            float d2 = ez[j] - m.z;
            float d3 = ew[j] - m.w;
            float sq = d0 * d0 + d1 * d1 + d2 * d2 + d3 * d3;
            float dist = sqrtf(fmaxf(sq, 1e-12f));
            float h = fmaxf(dist - DELTA_V, 0.f);
            acc += s_vf[lab] * h * h;
        }
    }

    const unsigned fm = 0xffffffffu;
#pragma unroll
    for (int o = 16; o > 0; o >>= 1) acc += __shfl_xor_sync(fm, acc, o);
    __shared__ float s_w[TPB / 32];
    if ((threadIdx.x & 31) == 0) s_w[threadIdx.x >> 5] = acc;
    __syncthreads();
    if (threadIdx.x == 0) {
        float s = 0.f;
#pragma unroll
        for (int w = 0; w < TPB / 32; w++) s += s_w[w];
        g_pdist[blockIdx.x] = s;
    }
}

// ================= kernel 4: push loss + final combine (1 block) ============
__global__ void k_final(float* __restrict__ out) {
    int tid = threadIdx.x;  // 256
    __shared__ float s_d[TPB];
    // deterministic strided sum of dist partials
    float ds = 0.f;
    for (int i = tid; i < NBLK; i += TPB) ds += g_pdist[i];
    s_d[tid] = ds;
    __syncthreads();
    for (int s = TPB / 2; s > 0; s >>= 1) {
        if (tid < s) s_d[tid] += s_d[tid + s];
        __syncthreads();
    }

    __shared__ float s_var, s_has, s_pc;
    if (tid < 32) {
        int b = tid;  // one batch per lane
        float m[LL][CC];
        float v[LL];
#pragma unroll
        for (int l = 0; l < LL; l++) {
            v[l] = g_validf[b][l + 1];
#pragma unroll
            for (int c = 0; c < CC; c++) m[l][c] = g_means4[b][l + 1][c];
        }
        float psum = 0.f, np = 0.f;
#pragma unroll
        for (int i = 0; i < LL; i++) {
#pragma unroll
            for (int j = i + 1; j < LL; j++) {
                if (v[i] > 0.f && v[j] > 0.f) {
                    float sq = 0.f;
#pragma unroll
                    for (int c = 0; c < CC; c++) {
                        float d = m[i][c] - m[j][c];
                        sq += d * d;
                    }
                    float pd = sqrtf(fmaxf(sq, 1e-12f));
                    float ph = fmaxf(DELTA_D - pd, 0.f);
                    psum += ph * ph;
                    np += 1.f;
                }
            }
        }
        float var_b = (np > 0.f) ? (psum / np) : 0.f;
        float has   = (np > 0.f) ? 1.f : 0.f;
        float pc    = g_pc[b];
        const unsigned fm = 0xffffffffu;
#pragma unroll
        for (int o = 16; o > 0; o >>= 1) {
            var_b += __shfl_xor_sync(fm, var_b, o);
            has   += __shfl_xor_sync(fm, has, o);
            pc    += __shfl_xor_sync(fm, pc, o);
        }
        if (tid == 0) { s_var = var_b; s_has = has; s_pc = pc; }
    }
    __syncthreads();
    if (tid == 0) {
        float var_loss = (s_has > 0.f) ? (s_var / s_has) : 0.f;
        float dl = (s_pc > 0.f) ? (s_d[0] / fmaxf(s_pc, 1.f)) : 0.f;
        out[0] = dl + var_loss;
    }
}

extern "C" void kernel_launch(void* const* d_in, const int* in_sizes, int n_in,
                              void* d_out, int out_size) {
    const int*   targets = (const int*)d_in[0];
    const float* emb     = (const float*)d_in[1];
    float*       out     = (float*)d_out;

    k_accum<<<NBLK, TPB>>>(targets, emb);
    k_means<<<BB, TPB>>>();
    k_dist<<<NBLK, TPB>>>(targets, emb);
    k_final<<<1, TPB>>>(out);
}